// round 13
// baseline (speedup 1.0000x reference)
#include <cuda_runtime.h>
#include <cuda_fp16.h>
#include <cstdint>

#define HIDDEN 1024
#define HEADS 16
#define DH 64
#define RANK 8
#define SEQ 2048
#define BT 2
#define MROWS (BT*SEQ)          // 4096
#define KAUG 1088               // 1024 + 8 lora + 1 bias + 55 pad
#define NCHUNK 17               // KAUG / 64
#define LORA_SCALING 2.0f
#define QK_SCALE 0.125f
#define LOG2E 1.4426950408889634f

// ---------------- device scratch ----------------
__device__ __half g_qh[MROWS * HIDDEN];
__device__ __half g_kh[MROWS * HIDDEN];
__device__ __half g_vh[MROWS * HIDDEN];
__device__ __half g_xa[3ull * MROWS * KAUG];   // [x | 2*low | 1 | 0] fp16
__device__ __half g_wa[3ull * HIDDEN * KAUG];  // [W | Bl | b | 0]*outscale fp16

// ---------------- helpers ----------------
__device__ __forceinline__ uint32_t smem_u32(const void* p) {
    return (uint32_t)__cvta_generic_to_shared(p);
}
__device__ __forceinline__ void cp16(uint32_t dst, const void* src) {
    asm volatile("cp.async.cg.shared.global [%0], [%1], 16;\n" :: "r"(dst), "l"(src));
}
__device__ __forceinline__ void cp_commit() { asm volatile("cp.async.commit_group;\n"); }
__device__ __forceinline__ void cp_wait0()  { asm volatile("cp.async.wait_group 0;\n"); }

__device__ __forceinline__ void ldm_x4(uint32_t& r0, uint32_t& r1, uint32_t& r2, uint32_t& r3, uint32_t a) {
    asm volatile("ldmatrix.sync.aligned.m8n8.x4.shared.b16 {%0,%1,%2,%3}, [%4];\n"
                 : "=r"(r0), "=r"(r1), "=r"(r2), "=r"(r3) : "r"(a));
}
__device__ __forceinline__ void ldm_x4_t(uint32_t& r0, uint32_t& r1, uint32_t& r2, uint32_t& r3, uint32_t a) {
    asm volatile("ldmatrix.sync.aligned.m8n8.x4.trans.shared.b16 {%0,%1,%2,%3}, [%4];\n"
                 : "=r"(r0), "=r"(r1), "=r"(r2), "=r"(r3) : "r"(a));
}
__device__ __forceinline__ void mma16816(float* c, const uint32_t* a, uint32_t b0, uint32_t b1) {
    asm volatile(
        "mma.sync.aligned.m16n8k16.row.col.f32.f16.f16.f32 "
        "{%0,%1,%2,%3},{%4,%5,%6,%7},{%8,%9},{%0,%1,%2,%3};\n"
        : "+f"(c[0]), "+f"(c[1]), "+f"(c[2]), "+f"(c[3])
        : "r"(a[0]), "r"(a[1]), "r"(a[2]), "r"(a[3]), "r"(b0), "r"(b1));
}
__device__ __forceinline__ float ex2f(float x) {
    float y; asm("ex2.approx.ftz.f32 %0, %1;" : "=f"(y) : "f"(x)); return y;
}
__device__ __forceinline__ uint32_t h2u(float x, float y) {
    __half2 h = __floats2half2_rn(x, y);
    return *reinterpret_cast<uint32_t*>(&h);
}

// swizzles (16B granularity). SWZ: 128B rows. BSWZ: 256B rows.
#define SWZ(o)  ((o) ^ (((o) >> 3) & 0x70))
#define BSWZ(o) ((o) ^ (((o) >> 3) & 0xE0))

// ---------------- kernel 1: fused LoRA-low + augmented-X build ----------------
__global__ __launch_bounds__(256) void lora_augx_kernel(
    const float* __restrict__ xq, const float* __restrict__ xk, const float* __restrict__ xv,
    const float* __restrict__ Aq, const float* __restrict__ Ak, const float* __restrict__ Av) {
    __shared__ float lowsm[RANK];
    int row = blockIdx.x, p = blockIdx.y;
    const float* x = (p == 0) ? xq : ((p == 1) ? xk : xv);
    const float* A = (p == 0) ? Aq : ((p == 1) ? Ak : Av);
    int tid = threadIdx.x, w = tid >> 5, l = tid & 31;
    const float* xr = x + (size_t)row * HIDDEN;
    const float4* xr4 = (const float4*)xr;
    const float4* Ar4 = (const float4*)(A + (size_t)w * HIDDEN);
    float s = 0.f;
    #pragma unroll
    for (int i = l; i < HIDDEN / 4; i += 32) {
        float4 a = xr4[i], b = Ar4[i];
        s += a.x * b.x + a.y * b.y + a.z * b.z + a.w * b.w;
    }
    s += __shfl_xor_sync(0xffffffffu, s, 16);
    s += __shfl_xor_sync(0xffffffffu, s, 8);
    s += __shfl_xor_sync(0xffffffffu, s, 4);
    s += __shfl_xor_sync(0xffffffffu, s, 2);
    s += __shfl_xor_sync(0xffffffffu, s, 1);
    if (l == 0) lowsm[w] = s;
    __syncthreads();

    __half* dst = g_xa + ((size_t)p * MROWS + row) * KAUG;
    int c0 = tid * 4;
    float4 a = *(const float4*)(xr + c0);
    *(__half2*)(dst + c0)     = __floats2half2_rn(a.x, a.y);
    *(__half2*)(dst + c0 + 2) = __floats2half2_rn(a.z, a.w);
    if (tid < 16) {
        float vv[4];
        #pragma unroll
        for (int i = 0; i < 4; i++) {
            int idx = tid * 4 + i;
            vv[i] = (idx < RANK) ? LORA_SCALING * lowsm[idx] : (idx == RANK ? 1.0f : 0.0f);
        }
        __half* dt = dst + HIDDEN + tid * 4;
        *(__half2*)(dt)     = __floats2half2_rn(vv[0], vv[1]);
        *(__half2*)(dt + 2) = __floats2half2_rn(vv[2], vv[3]);
    }
}

// ---------------- kernel 2: augmented W = [W | Bl | b | 0]*outscale fp16 ----------------
__global__ void aug_w_kernel(const float* __restrict__ Wq, const float* __restrict__ Bq, const float* __restrict__ bq,
                             const float* __restrict__ Wk, const float* __restrict__ Bk, const float* __restrict__ bk,
                             const float* __restrict__ Wv, const float* __restrict__ Bv, const float* __restrict__ bv) {
    int r = blockIdx.x, p = blockIdx.y;
    const float* W  = (p == 0) ? Wq : (p == 1) ? Wk : Wv;
    const float* Bl = (p == 0) ? Bq : (p == 1) ? Bk : Bv;
    const float* bs = (p == 0) ? bq : (p == 1) ? bk : bv;
    float scale = (p == 0) ? QK_SCALE : 1.0f;
    const float* wr = W + (size_t)r * HIDDEN;
    __half* dst = g_wa + ((size_t)p * HIDDEN + r) * KAUG;
    for (int c0 = threadIdx.x * 4; c0 < KAUG; c0 += blockDim.x * 4) {
        if (c0 < HIDDEN) {
            float4 a = *(const float4*)(wr + c0);
            *(__half2*)(dst + c0)     = __floats2half2_rn(a.x * scale, a.y * scale);
            *(__half2*)(dst + c0 + 2) = __floats2half2_rn(a.z * scale, a.w * scale);
        } else {
            float vv[4];
            #pragma unroll
            for (int i = 0; i < 4; i++) {
                int idx = c0 + i - HIDDEN;
                vv[i] = (idx < RANK) ? Bl[(size_t)r * RANK + idx] * scale
                                     : (idx == RANK ? bs[r] * scale : 0.0f);
            }
            *(__half2*)(dst + c0)     = __floats2half2_rn(vv[0], vv[1]);
            *(__half2*)(dst + c0 + 2) = __floats2half2_rn(vv[2], vv[3]);
        }
    }
}

// ---------------- kernel 3: fused projection GEMM (HMMA), N=3072 ----------------
// BM=128 BN=128 BK=64, 8 warps (2m x 4n), warp tile 64x32, 2 CTAs/SM, 2-stage.
#define PJ_STAGE 32768   // A 16KB + B 16KB per stage
__global__ __launch_bounds__(256, 2) void proj_kernel() {
    extern __shared__ __align__(1024) char psm[];
    uint32_t sb = smem_u32(psm);

    int tid = threadIdx.x, w = tid >> 5, l = tid & 31;
    int m0 = blockIdx.y * 128;
    int ng = blockIdx.x * 128;
    int sel = ng >> 10;
    int n0 = ng & 1023;
    const __half* Xa = g_xa + (size_t)sel * MROWS * KAUG;
    const __half* Wa = g_wa + (size_t)sel * HIDDEN * KAUG;
    __half* outp = (sel == 0) ? g_qh : (sel == 1) ? g_kh : g_vh;

    int wm = (w >> 2) * 64, wn = (w & 3) * 32;

    float acc[4][4][4];
    #pragma unroll
    for (int i = 0; i < 4; i++)
        #pragma unroll
        for (int j = 0; j < 4; j++)
            #pragma unroll
            for (int q2 = 0; q2 < 4; q2++) acc[i][j][q2] = 0.f;

    auto load_stage = [&](int kt, int s) {
        uint32_t abase = sb + (uint32_t)s * PJ_STAGE;
        uint32_t bbase = abase + 16384;
        int kof = kt * 64;
        #pragma unroll
        for (int i = 0; i < 4; i++) {
            int ch = tid + 256 * i;
            int r = ch >> 3, j = ch & 7;
            cp16(abase + SWZ((uint32_t)(r * 128 + j * 16)),
                 Xa + (size_t)(m0 + r) * KAUG + kof + j * 8);
        }
        #pragma unroll
        for (int i = 0; i < 4; i++) {
            int ch = tid + 256 * i;
            int r = ch >> 3, j = ch & 7;
            cp16(bbase + SWZ((uint32_t)(r * 128 + j * 16)),
                 Wa + (size_t)(n0 + r) * KAUG + kof + j * 8);
        }
        cp_commit();
    };

    load_stage(0, 0);

    for (int kt = 0; kt < NCHUNK; kt++) {
        cp_wait0();
        __syncthreads();
        int buf = kt & 1;
        if (kt + 1 < NCHUNK) load_stage(kt + 1, buf ^ 1);

        uint32_t ab = sb + (uint32_t)buf * PJ_STAGE;
        uint32_t bb = ab + 16384;

        #pragma unroll
        for (int kf = 0; kf < 4; kf++) {
            uint32_t a[4][4];
            #pragma unroll
            for (int mf = 0; mf < 4; mf++) {
                uint32_t off = SWZ((uint32_t)(((wm + mf * 16 + (l & 15)) * 64 + kf * 16 + (l >> 4) * 8) * 2));
                ldm_x4(a[mf][0], a[mf][1], a[mf][2], a[mf][3], ab + off);
            }
            #pragma unroll
            for (int np = 0; np < 2; np++) {
                uint32_t b0, b1, b2, b3;
                int row = wn + np * 16 + (l & 7) + ((l >> 4) << 3);
                int col = kf * 16 + ((l >> 3) & 1) * 8;
                ldm_x4(b0, b1, b2, b3, bb + SWZ((uint32_t)((row * 64 + col) * 2)));
                #pragma unroll
                for (int mf = 0; mf < 4; mf++) {
                    mma16816(acc[mf][2 * np],     a[mf], b0, b1);
                    mma16816(acc[mf][2 * np + 1], a[mf], b2, b3);
                }
            }
        }
    }

    #pragma unroll
    for (int mf = 0; mf < 4; mf++) {
        #pragma unroll
        for (int rr = 0; rr < 2; rr++) {
            int r = m0 + wm + mf * 16 + (l >> 2) + rr * 8;
            #pragma unroll
            for (int nf = 0; nf < 4; nf++) {
                int c = n0 + wn + nf * 8 + 2 * (l & 3);
                *(__half2*)(outp + (size_t)r * HIDDEN + c) =
                    __floats2half2_rn(acc[mf][nf][rr * 2], acc[mf][nf][rr * 2 + 1]);
            }
        }
    }
}

// ---------------- kernel 4: attention, 8 warps (split-N), 2 CTAs/SM -> 16 warps/SM ----------------
// warp (wq = w&3, wk = w>>2): q-rows [wq*16, +16), k-cols [wk*32, +32).
// smem: Q 8KB | K 2x8KB | V 2x8KB | bias 2x16KB = 73728 B. After the loop the
// region is reused for O-partial / row-sum exchange between warp pairs (wk 0/1).
#define AT_Q 0
#define AT_K 8192
#define AT_V 24576
#define AT_B 40960
#define AT_SMEM 73728
#define XROWB 288   // exchange row stride (bytes) to break bank conflicts

__global__ __launch_bounds__(256, 2) void attn_kernel(const float* __restrict__ bias,
                                                      float* __restrict__ out) {
    extern __shared__ __align__(1024) char asm_[];
    uint32_t sb = smem_u32(asm_);

    int tid = threadIdx.x, w = tid >> 5, l = tid & 31;
    int wq = w & 3, wk = w >> 2;
    int q0 = blockIdx.x * 64;
    int h  = blockIdx.y;
    int b  = blockIdx.z;

    const __half* qbase = g_qh + ((size_t)(b * SEQ + q0)) * HIDDEN + h * DH;
    const __half* kbase = g_kh + ((size_t)(b * SEQ)) * HIDDEN + h * DH;
    const __half* vbase = g_vh + ((size_t)(b * SEQ)) * HIDDEN + h * DH;
    const float*  bglob = bias + ((size_t)(b * HEADS + h) * SEQ + q0) * SEQ;

    // prologue: Q (512 chunks) + K0/V0/bias0 (2048 chunks) in one group
    #pragma unroll
    for (int i = 0; i < 2; i++) {
        int ch = tid + 256 * i;
        int r = ch >> 3, j = ch & 7;
        cp16(sb + AT_Q + SWZ((uint32_t)(r * 128 + j * 16)), qbase + (size_t)r * HIDDEN + j * 8);
    }
    #pragma unroll
    for (int i = 0; i < 8; i++) {
        int ch = tid + 256 * i;
        if (ch < 512) {
            int r = ch >> 3, j = ch & 7;
            cp16(sb + AT_K + SWZ((uint32_t)(r * 128 + j * 16)), kbase + (size_t)r * HIDDEN + j * 8);
        } else if (ch < 1024) {
            int c2 = ch - 512, r = c2 >> 3, j = c2 & 7;
            cp16(sb + AT_V + SWZ((uint32_t)(r * 128 + j * 16)), vbase + (size_t)r * HIDDEN + j * 8);
        } else {
            int c2 = ch - 1024, r = c2 >> 4, j = c2 & 15;
            cp16(sb + AT_B + BSWZ((uint32_t)(r * 256 + j * 16)), bglob + (size_t)r * SEQ + j * 4);
        }
    }
    cp_commit();

    uint32_t qa[4][4];
    float o[8][4];
    #pragma unroll
    for (int i = 0; i < 8; i++)
        #pragma unroll
        for (int j = 0; j < 4; j++) o[i][j] = 0.f;
    float lrow0 = 0.f, lrow1 = 0.f;
    int rb0 = wq * 16 + (l >> 2);

    for (int kt = 0; kt < SEQ / 64; kt++) {
        cp_wait0();
        __syncthreads();
        int buf = kt & 1;

        if (kt == 0) {
            #pragma unroll
            for (int kf = 0; kf < 4; kf++) {
                uint32_t off = SWZ((uint32_t)((wq * 16 + (l & 15)) * 128 + (kf * 16 + (l >> 4) * 8) * 2));
                ldm_x4(qa[kf][0], qa[kf][1], qa[kf][2], qa[kf][3], sb + AT_Q + off);
            }
        }
        if (kt + 1 < SEQ / 64) {
            int nb = buf ^ 1;
            uint32_t ko = sb + AT_K + (uint32_t)(nb * 8192);
            uint32_t vo = sb + AT_V + (uint32_t)(nb * 8192);
            uint32_t bo = sb + AT_B + (uint32_t)(nb * 16384);
            const __half* kb = kbase + (size_t)((kt + 1) * 64) * HIDDEN;
            const __half* vb = vbase + (size_t)((kt + 1) * 64) * HIDDEN;
            const float*  bb = bglob + (size_t)(kt + 1) * 64;
            #pragma unroll
            for (int i = 0; i < 8; i++) {
                int ch = tid + 256 * i;
                if (ch < 512) {
                    int r = ch >> 3, j = ch & 7;
                    cp16(ko + SWZ((uint32_t)(r * 128 + j * 16)), kb + (size_t)r * HIDDEN + j * 8);
                } else if (ch < 1024) {
                    int c2 = ch - 512, r = c2 >> 3, j = c2 & 7;
                    cp16(vo + SWZ((uint32_t)(r * 128 + j * 16)), vb + (size_t)r * HIDDEN + j * 8);
                } else {
                    int c2 = ch - 1024, r = c2 >> 4, j = c2 & 15;
                    cp16(bo + BSWZ((uint32_t)(r * 256 + j * 16)), bb + (size_t)r * SEQ + j * 4);
                }
            }
            cp_commit();
        }

        uint32_t kbuf = sb + AT_K + (uint32_t)(buf * 8192);
        uint32_t vbuf = sb + AT_V + (uint32_t)(buf * 8192);

        // S = Q K^T for this warp's 16 q-rows x 32 k-cols
        float sc[4][4];
        #pragma unroll
        for (int i = 0; i < 4; i++)
            #pragma unroll
            for (int j = 0; j < 4; j++) sc[i][j] = 0.f;

        #pragma unroll
        for (int np = 0; np < 2; np++) {
            #pragma unroll
            for (int kf = 0; kf < 4; kf++) {
                uint32_t b0, b1, b2, b3;
                int row = wk * 32 + np * 16 + (l & 7) + ((l >> 4) << 3);
                int col = kf * 16 + ((l >> 3) & 1) * 8;
                ldm_x4(b0, b1, b2, b3, kbuf + SWZ((uint32_t)((row * 64 + col) * 2)));
                mma16816(sc[2 * np],     qa[kf], b0, b1);
                mma16816(sc[2 * np + 1], qa[kf], b2, b3);
            }
        }

        // P = exp(S + bias) without max-shift (scores bounded ~|10|)
        {
            const char* bsm = asm_ + AT_B + buf * 16384;
            #pragma unroll
            for (int j = 0; j < 4; j++) {
                uint32_t o0 = (uint32_t)(rb0 * 256 + wk * 128 + j * 32 + (l & 3) * 8);
                uint32_t o1 = o0 + 8 * 256;
                float2 v0 = *(const float2*)(bsm + BSWZ(o0));
                float2 v1 = *(const float2*)(bsm + BSWZ(o1));
                sc[j][0] = ex2f((sc[j][0] + v0.x) * LOG2E);
                sc[j][1] = ex2f((sc[j][1] + v0.y) * LOG2E);
                sc[j][2] = ex2f((sc[j][2] + v1.x) * LOG2E);
                sc[j][3] = ex2f((sc[j][3] + v1.y) * LOG2E);
                lrow0 += sc[j][0] + sc[j][1];
                lrow1 += sc[j][2] + sc[j][3];
            }
        }

        // P -> fp16 A fragments (k = warp's 32 cols, 2 k16 groups)
        uint32_t pa[2][4];
        #pragma unroll
        for (int kf = 0; kf < 2; kf++) {
            pa[kf][0] = h2u(sc[2 * kf][0],     sc[2 * kf][1]);
            pa[kf][1] = h2u(sc[2 * kf][2],     sc[2 * kf][3]);
            pa[kf][2] = h2u(sc[2 * kf + 1][0], sc[2 * kf + 1][1]);
            pa[kf][3] = h2u(sc[2 * kf + 1][2], sc[2 * kf + 1][3]);
        }

        // O += P V (partial over this warp's k-range; full 64 d-cols)
        #pragma unroll
        for (int np = 0; np < 4; np++) {
            #pragma unroll
            for (int kf = 0; kf < 2; kf++) {
                uint32_t b0, b1, b2, b3;
                int row = wk * 32 + kf * 16 + (l & 7) + (((l >> 3) & 1) << 3);
                int col = np * 16 + ((l >> 4) << 3);
                ldm_x4_t(b0, b1, b2, b3, vbuf + SWZ((uint32_t)((row * 64 + col) * 2)));
                mma16816(o[2 * np],     pa[kf], b0, b1);
                mma16816(o[2 * np + 1], pa[kf], b2, b3);
            }
        }
    }

    // ---- combine warp pairs (wk=0 + wk=1) via smem ----
    __syncthreads();   // all loop reads done; smem reusable

    // quad-reduce partial row sums (cols within quad)
    lrow0 += __shfl_xor_sync(0xffffffffu, lrow0, 1);
    lrow0 += __shfl_xor_sync(0xffffffffu, lrow0, 2);
    lrow1 += __shfl_xor_sync(0xffffffffu, lrow1, 1);
    lrow1 += __shfl_xor_sync(0xffffffffu, lrow1, 2);

    float* XS = (float*)asm_;                       // sums[2][64] (512 B)
    char*  XO = asm_ + 1024;                        // O partials: 4 x 16 x XROWB
    if ((l & 3) == 0) {
        XS[wk * 64 + rb0]     = lrow0;
        XS[wk * 64 + rb0 + 8] = lrow1;
    }
    if (wk == 1) {
        char* base = XO + wq * (16 * XROWB) + (l >> 2) * XROWB;
        #pragma unroll
        for (int np = 0; np < 4; np++) {
            char* c0 = base + (np * 16 + 2 * (l & 3)) * 4;
            *(float2*)(c0)              = make_float2(o[2 * np][0], o[2 * np][1]);
            *(float2*)(c0 + 8 * XROWB)  = make_float2(o[2 * np][2], o[2 * np][3]);
            char* c1 = c0 + 32;
            *(float2*)(c1)              = make_float2(o[2 * np + 1][0], o[2 * np + 1][1]);
            *(float2*)(c1 + 8 * XROWB)  = make_float2(o[2 * np + 1][2], o[2 * np + 1][3]);
        }
    }
    __syncthreads();

    if (wk == 0) {
        float s0 = XS[rb0]     + XS[64 + rb0];
        float s1 = XS[rb0 + 8] + XS[64 + rb0 + 8];
        float inv0 = 1.f / s0, inv1 = 1.f / s1;
        char* base = XO + wq * (16 * XROWB) + (l >> 2) * XROWB;
        float* ob = out + ((size_t)(b * SEQ + q0 + rb0)) * HIDDEN + h * DH + 2 * (l & 3);
        #pragma unroll
        for (int np = 0; np < 4; np++) {
            char* c0 = base + (np * 16 + 2 * (l & 3)) * 4;
            float2 p00 = *(float2*)(c0);
            float2 p01 = *(float2*)(c0 + 8 * XROWB);
            char* c1 = c0 + 32;
            float2 p10 = *(float2*)(c1);
            float2 p11 = *(float2*)(c1 + 8 * XROWB);
            *(float2*)(ob + (2 * np) * 8) =
                make_float2((o[2 * np][0] + p00.x) * inv0, (o[2 * np][1] + p00.y) * inv0);
            *(float2*)(ob + 8 * (size_t)HIDDEN + (2 * np) * 8) =
                make_float2((o[2 * np][2] + p01.x) * inv1, (o[2 * np][3] + p01.y) * inv1);
            *(float2*)(ob + (2 * np + 1) * 8) =
                make_float2((o[2 * np + 1][0] + p10.x) * inv0, (o[2 * np + 1][1] + p10.y) * inv0);
            *(float2*)(ob + 8 * (size_t)HIDDEN + (2 * np + 1) * 8) =
                make_float2((o[2 * np + 1][2] + p11.x) * inv1, (o[2 * np + 1][3] + p11.y) * inv1);
        }
    }
}

// ---------------- launch (serialized) ----------------
extern "C" void kernel_launch(void* const* d_in, const int* in_sizes, int n_in,
                              void* d_out, int out_size) {
    (void)in_sizes; (void)n_in; (void)out_size;
    const float* q  = (const float*)d_in[0];
    const float* k  = (const float*)d_in[1];
    const float* v  = (const float*)d_in[2];
    const float* ab = (const float*)d_in[3];
    const float* Wq = (const float*)d_in[4];
    const float* bq = (const float*)d_in[5];
    const float* Aq = (const float*)d_in[6];
    const float* Bq = (const float*)d_in[7];
    const float* Wk = (const float*)d_in[8];
    const float* bk = (const float*)d_in[9];
    const float* Ak = (const float*)d_in[10];
    const float* Bk = (const float*)d_in[11];
    const float* Wv = (const float*)d_in[12];
    const float* bv = (const float*)d_in[13];
    const float* Av = (const float*)d_in[14];
    const float* Bv = (const float*)d_in[15];
    float* out = (float*)d_out;

    cudaFuncSetAttribute(proj_kernel, cudaFuncAttributeMaxDynamicSharedMemorySize, 2 * PJ_STAGE);
    cudaFuncSetAttribute(attn_kernel, cudaFuncAttributeMaxDynamicSharedMemorySize, AT_SMEM);

    aug_w_kernel<<<dim3(HIDDEN, 3), 256>>>(Wq, Bq, bq, Wk, Bk, bk, Wv, Bv, bv);
    lora_augx_kernel<<<dim3(MROWS, 3), 256>>>(q, k, v, Aq, Ak, Av);

    proj_kernel<<<dim3(3 * HIDDEN / 128, MROWS / 128), 256, 2 * PJ_STAGE>>>();

    attn_kernel<<<dim3(SEQ / 64, HEADS, BT), 256, AT_SMEM>>>(ab, out);
}

// round 14
// speedup vs baseline: 1.0886x; 1.0886x over previous
#include <cuda_runtime.h>
#include <cuda_fp16.h>
#include <cstdint>

#define HIDDEN 1024
#define HEADS 16
#define DH 64
#define RANK 8
#define SEQ 2048
#define BT 2
#define MROWS (BT*SEQ)          // 4096
#define KAUG 1088               // 1024 + 8 lora + 1 bias + 55 pad
#define NCHUNK 17               // KAUG / 64
#define LORA_SCALING 2.0f
#define QK_SCALE 0.125f
#define LOG2E 1.4426950408889634f

// ---------------- device scratch ----------------
__device__ __half g_qh[MROWS * HIDDEN];
__device__ __half g_kh[MROWS * HIDDEN];
__device__ __half g_vh[MROWS * HIDDEN];
__device__ __half g_xa[3ull * MROWS * KAUG];   // [x | 2*low | 1 | 0] fp16
__device__ __half g_wa[3ull * HIDDEN * KAUG];  // [W | Bl | b | 0]*outscale fp16

// ---------------- helpers ----------------
__device__ __forceinline__ uint32_t smem_u32(const void* p) {
    return (uint32_t)__cvta_generic_to_shared(p);
}
__device__ __forceinline__ void cp16(uint32_t dst, const void* src) {
    asm volatile("cp.async.cg.shared.global [%0], [%1], 16;\n" :: "r"(dst), "l"(src));
}
__device__ __forceinline__ void cp_commit() { asm volatile("cp.async.commit_group;\n"); }
__device__ __forceinline__ void cp_wait0()  { asm volatile("cp.async.wait_group 0;\n"); }

__device__ __forceinline__ void ldm_x4(uint32_t& r0, uint32_t& r1, uint32_t& r2, uint32_t& r3, uint32_t a) {
    asm volatile("ldmatrix.sync.aligned.m8n8.x4.shared.b16 {%0,%1,%2,%3}, [%4];\n"
                 : "=r"(r0), "=r"(r1), "=r"(r2), "=r"(r3) : "r"(a));
}
__device__ __forceinline__ void ldm_x4_t(uint32_t& r0, uint32_t& r1, uint32_t& r2, uint32_t& r3, uint32_t a) {
    asm volatile("ldmatrix.sync.aligned.m8n8.x4.trans.shared.b16 {%0,%1,%2,%3}, [%4];\n"
                 : "=r"(r0), "=r"(r1), "=r"(r2), "=r"(r3) : "r"(a));
}
__device__ __forceinline__ void mma16816(float* c, const uint32_t* a, uint32_t b0, uint32_t b1) {
    asm volatile(
        "mma.sync.aligned.m16n8k16.row.col.f32.f16.f16.f32 "
        "{%0,%1,%2,%3},{%4,%5,%6,%7},{%8,%9},{%0,%1,%2,%3};\n"
        : "+f"(c[0]), "+f"(c[1]), "+f"(c[2]), "+f"(c[3])
        : "r"(a[0]), "r"(a[1]), "r"(a[2]), "r"(a[3]), "r"(b0), "r"(b1));
}
__device__ __forceinline__ float ex2f(float x) {
    float y; asm("ex2.approx.ftz.f32 %0, %1;" : "=f"(y) : "f"(x)); return y;
}
__device__ __forceinline__ uint32_t h2u(float x, float y) {
    __half2 h = __floats2half2_rn(x, y);
    return *reinterpret_cast<uint32_t*>(&h);
}

// swizzles (16B granularity). SWZ: 128B rows. BSWZ: 256B rows.
#define SWZ(o)  ((o) ^ (((o) >> 3) & 0x70))
#define BSWZ(o) ((o) ^ (((o) >> 3) & 0xE0))

// ---------------- kernel 1: fused LoRA-low + augmented-X build ----------------
__global__ __launch_bounds__(256) void lora_augx_kernel(
    const float* __restrict__ xq, const float* __restrict__ xk, const float* __restrict__ xv,
    const float* __restrict__ Aq, const float* __restrict__ Ak, const float* __restrict__ Av) {
    __shared__ float lowsm[RANK];
    int row = blockIdx.x, p = blockIdx.y;
    const float* x = (p == 0) ? xq : ((p == 1) ? xk : xv);
    const float* A = (p == 0) ? Aq : ((p == 1) ? Ak : Av);
    int tid = threadIdx.x, w = tid >> 5, l = tid & 31;
    const float* xr = x + (size_t)row * HIDDEN;
    const float4* xr4 = (const float4*)xr;
    const float4* Ar4 = (const float4*)(A + (size_t)w * HIDDEN);
    float s = 0.f;
    #pragma unroll
    for (int i = l; i < HIDDEN / 4; i += 32) {
        float4 a = xr4[i], b = Ar4[i];
        s += a.x * b.x + a.y * b.y + a.z * b.z + a.w * b.w;
    }
    s += __shfl_xor_sync(0xffffffffu, s, 16);
    s += __shfl_xor_sync(0xffffffffu, s, 8);
    s += __shfl_xor_sync(0xffffffffu, s, 4);
    s += __shfl_xor_sync(0xffffffffu, s, 2);
    s += __shfl_xor_sync(0xffffffffu, s, 1);
    if (l == 0) lowsm[w] = s;
    __syncthreads();

    __half* dst = g_xa + ((size_t)p * MROWS + row) * KAUG;
    int c0 = tid * 4;
    float4 a = *(const float4*)(xr + c0);
    *(__half2*)(dst + c0)     = __floats2half2_rn(a.x, a.y);
    *(__half2*)(dst + c0 + 2) = __floats2half2_rn(a.z, a.w);
    if (tid < 16) {
        float vv[4];
        #pragma unroll
        for (int i = 0; i < 4; i++) {
            int idx = tid * 4 + i;
            vv[i] = (idx < RANK) ? LORA_SCALING * lowsm[idx] : (idx == RANK ? 1.0f : 0.0f);
        }
        __half* dt = dst + HIDDEN + tid * 4;
        *(__half2*)(dt)     = __floats2half2_rn(vv[0], vv[1]);
        *(__half2*)(dt + 2) = __floats2half2_rn(vv[2], vv[3]);
    }
}

// ---------------- kernel 2: augmented W = [W | Bl | b | 0]*outscale fp16 ----------------
__global__ void aug_w_kernel(const float* __restrict__ Wq, const float* __restrict__ Bq, const float* __restrict__ bq,
                             const float* __restrict__ Wk, const float* __restrict__ Bk, const float* __restrict__ bk,
                             const float* __restrict__ Wv, const float* __restrict__ Bv, const float* __restrict__ bv) {
    int r = blockIdx.x, p = blockIdx.y;
    const float* W  = (p == 0) ? Wq : (p == 1) ? Wk : Wv;
    const float* Bl = (p == 0) ? Bq : (p == 1) ? Bk : Bv;
    const float* bs = (p == 0) ? bq : (p == 1) ? bk : bv;
    float scale = (p == 0) ? QK_SCALE : 1.0f;
    const float* wr = W + (size_t)r * HIDDEN;
    __half* dst = g_wa + ((size_t)p * HIDDEN + r) * KAUG;
    for (int c0 = threadIdx.x * 4; c0 < KAUG; c0 += blockDim.x * 4) {
        if (c0 < HIDDEN) {
            float4 a = *(const float4*)(wr + c0);
            *(__half2*)(dst + c0)     = __floats2half2_rn(a.x * scale, a.y * scale);
            *(__half2*)(dst + c0 + 2) = __floats2half2_rn(a.z * scale, a.w * scale);
        } else {
            float vv[4];
            #pragma unroll
            for (int i = 0; i < 4; i++) {
                int idx = c0 + i - HIDDEN;
                vv[i] = (idx < RANK) ? Bl[(size_t)r * RANK + idx] * scale
                                     : (idx == RANK ? bs[r] * scale : 0.0f);
            }
            *(__half2*)(dst + c0)     = __floats2half2_rn(vv[0], vv[1]);
            *(__half2*)(dst + c0 + 2) = __floats2half2_rn(vv[2], vv[3]);
        }
    }
}

// ---------------- kernel 3: fused projection GEMM (HMMA), N=3072 ----------------
// BM=128 BN=128 BK=64, 8 warps (2m x 4n), warp tile 64x32, 2 CTAs/SM, 2-stage.
// Last K-chunk peeled: real data ends at col 1033, so only kf=0 computes there.
#define PJ_STAGE 32768   // A 16KB + B 16KB per stage
__global__ __launch_bounds__(256, 2) void proj_kernel() {
    extern __shared__ __align__(1024) char psm[];
    uint32_t sb = smem_u32(psm);

    int tid = threadIdx.x, w = tid >> 5, l = tid & 31;
    int m0 = blockIdx.y * 128;
    int ng = blockIdx.x * 128;
    int sel = ng >> 10;
    int n0 = ng & 1023;
    const __half* Xa = g_xa + (size_t)sel * MROWS * KAUG;
    const __half* Wa = g_wa + (size_t)sel * HIDDEN * KAUG;
    __half* outp = (sel == 0) ? g_qh : (sel == 1) ? g_kh : g_vh;

    int wm = (w >> 2) * 64, wn = (w & 3) * 32;

    float acc[4][4][4];
    #pragma unroll
    for (int i = 0; i < 4; i++)
        #pragma unroll
        for (int j = 0; j < 4; j++)
            #pragma unroll
            for (int q2 = 0; q2 < 4; q2++) acc[i][j][q2] = 0.f;

    auto load_stage = [&](int kt, int s) {
        uint32_t abase = sb + (uint32_t)s * PJ_STAGE;
        uint32_t bbase = abase + 16384;
        int kof = kt * 64;
        #pragma unroll
        for (int i = 0; i < 4; i++) {
            int ch = tid + 256 * i;
            int r = ch >> 3, j = ch & 7;
            cp16(abase + SWZ((uint32_t)(r * 128 + j * 16)),
                 Xa + (size_t)(m0 + r) * KAUG + kof + j * 8);
        }
        #pragma unroll
        for (int i = 0; i < 4; i++) {
            int ch = tid + 256 * i;
            int r = ch >> 3, j = ch & 7;
            cp16(bbase + SWZ((uint32_t)(r * 128 + j * 16)),
                 Wa + (size_t)(n0 + r) * KAUG + kof + j * 8);
        }
        cp_commit();
    };

    load_stage(0, 0);

    for (int kt = 0; kt < NCHUNK - 1; kt++) {
        cp_wait0();
        __syncthreads();
        int buf = kt & 1;
        load_stage(kt + 1, buf ^ 1);

        uint32_t ab = sb + (uint32_t)buf * PJ_STAGE;
        uint32_t bb = ab + 16384;

        #pragma unroll
        for (int kf = 0; kf < 4; kf++) {
            uint32_t a[4][4];
            #pragma unroll
            for (int mf = 0; mf < 4; mf++) {
                uint32_t off = SWZ((uint32_t)(((wm + mf * 16 + (l & 15)) * 64 + kf * 16 + (l >> 4) * 8) * 2));
                ldm_x4(a[mf][0], a[mf][1], a[mf][2], a[mf][3], ab + off);
            }
            #pragma unroll
            for (int np = 0; np < 2; np++) {
                uint32_t b0, b1, b2, b3;
                int row = wn + np * 16 + (l & 7) + ((l >> 4) << 3);
                int col = kf * 16 + ((l >> 3) & 1) * 8;
                ldm_x4(b0, b1, b2, b3, bb + SWZ((uint32_t)((row * 64 + col) * 2)));
                #pragma unroll
                for (int mf = 0; mf < 4; mf++) {
                    mma16816(acc[mf][2 * np],     a[mf], b0, b1);
                    mma16816(acc[mf][2 * np + 1], a[mf], b2, b3);
                }
            }
        }
    }

    // tail chunk (kt = 16, buf = 0): cols 1024..1087, data only in first 16 -> kf=0
    cp_wait0();
    __syncthreads();
    {
        uint32_t ab = sb;
        uint32_t bb = ab + 16384;
        uint32_t a[4][4];
        #pragma unroll
        for (int mf = 0; mf < 4; mf++) {
            uint32_t off = SWZ((uint32_t)(((wm + mf * 16 + (l & 15)) * 64 + (l >> 4) * 8) * 2));
            ldm_x4(a[mf][0], a[mf][1], a[mf][2], a[mf][3], ab + off);
        }
        #pragma unroll
        for (int np = 0; np < 2; np++) {
            uint32_t b0, b1, b2, b3;
            int row = wn + np * 16 + (l & 7) + ((l >> 4) << 3);
            int col = ((l >> 3) & 1) * 8;
            ldm_x4(b0, b1, b2, b3, bb + SWZ((uint32_t)((row * 64 + col) * 2)));
            #pragma unroll
            for (int mf = 0; mf < 4; mf++) {
                mma16816(acc[mf][2 * np],     a[mf], b0, b1);
                mma16816(acc[mf][2 * np + 1], a[mf], b2, b3);
            }
        }
    }

    #pragma unroll
    for (int mf = 0; mf < 4; mf++) {
        #pragma unroll
        for (int rr = 0; rr < 2; rr++) {
            int r = m0 + wm + mf * 16 + (l >> 2) + rr * 8;
            #pragma unroll
            for (int nf = 0; nf < 4; nf++) {
                int c = n0 + wn + nf * 8 + 2 * (l & 3);
                *(__half2*)(outp + (size_t)r * HIDDEN + c) =
                    __floats2half2_rn(acc[mf][nf][rr * 2], acc[mf][nf][rr * 2 + 1]);
            }
        }
    }
}

// ---------------- kernel 4: attention (round-8 best shape), 4 warps, 3 CTAs/SM ----------------
// smem: Q 8KB | K 2x8KB | V 2x8KB | bias 2x16KB = 73728 B
#define AT_Q 0
#define AT_K 8192
#define AT_V 24576
#define AT_B 40960
#define AT_SMEM 73728

__global__ __launch_bounds__(128, 3) void attn_kernel(const float* __restrict__ bias,
                                                      float* __restrict__ out) {
    extern __shared__ __align__(1024) char asm_[];
    uint32_t sb = smem_u32(asm_);

    int tid = threadIdx.x, w = tid >> 5, l = tid & 31;
    int q0 = blockIdx.x * 64;
    int h  = blockIdx.y;
    int b  = blockIdx.z;

    const __half* qbase = g_qh + ((size_t)(b * SEQ + q0)) * HIDDEN + h * DH;
    const __half* kbase = g_kh + ((size_t)(b * SEQ)) * HIDDEN + h * DH;
    const __half* vbase = g_vh + ((size_t)(b * SEQ)) * HIDDEN + h * DH;
    const float*  bglob = bias + ((size_t)(b * HEADS + h) * SEQ + q0) * SEQ;

    // prologue: Q + K0/V0/bias0 in one group
    #pragma unroll
    for (int i = 0; i < 4; i++) {
        int ch = tid + 128 * i;
        int r = ch >> 3, j = ch & 7;
        cp16(sb + AT_Q + SWZ((uint32_t)(r * 128 + j * 16)), qbase + (size_t)r * HIDDEN + j * 8);
    }
    #pragma unroll
    for (int i = 0; i < 16; i++) {
        int ch = tid + 128 * i;
        if (ch < 512) {
            int r = ch >> 3, j = ch & 7;
            cp16(sb + AT_K + SWZ((uint32_t)(r * 128 + j * 16)), kbase + (size_t)r * HIDDEN + j * 8);
        } else if (ch < 1024) {
            int c2 = ch - 512, r = c2 >> 3, j = c2 & 7;
            cp16(sb + AT_V + SWZ((uint32_t)(r * 128 + j * 16)), vbase + (size_t)r * HIDDEN + j * 8);
        } else {
            int c2 = ch - 1024, r = c2 >> 4, j = c2 & 15;
            cp16(sb + AT_B + BSWZ((uint32_t)(r * 256 + j * 16)), bglob + (size_t)r * SEQ + j * 4);
        }
    }
    cp_commit();

    uint32_t qa[4][4];
    float o[8][4];
    #pragma unroll
    for (int i = 0; i < 8; i++)
        #pragma unroll
        for (int j = 0; j < 4; j++) o[i][j] = 0.f;
    float lrow0 = 0.f, lrow1 = 0.f;

    for (int kt = 0; kt < SEQ / 64; kt++) {
        cp_wait0();
        __syncthreads();
        int buf = kt & 1;

        if (kt == 0) {
            #pragma unroll
            for (int kf = 0; kf < 4; kf++) {
                uint32_t off = SWZ((uint32_t)((w * 16 + (l & 15)) * 128 + (kf * 16 + (l >> 4) * 8) * 2));
                ldm_x4(qa[kf][0], qa[kf][1], qa[kf][2], qa[kf][3], sb + AT_Q + off);
            }
        }
        if (kt + 1 < SEQ / 64) {
            int nb = buf ^ 1;
            uint32_t ko = sb + AT_K + (uint32_t)(nb * 8192);
            uint32_t vo = sb + AT_V + (uint32_t)(nb * 8192);
            uint32_t bo = sb + AT_B + (uint32_t)(nb * 16384);
            const __half* kb = kbase + (size_t)((kt + 1) * 64) * HIDDEN;
            const __half* vb = vbase + (size_t)((kt + 1) * 64) * HIDDEN;
            const float*  bb = bglob + (size_t)(kt + 1) * 64;
            #pragma unroll
            for (int i = 0; i < 16; i++) {
                int ch = tid + 128 * i;
                if (ch < 512) {
                    int r = ch >> 3, j = ch & 7;
                    cp16(ko + SWZ((uint32_t)(r * 128 + j * 16)), kb + (size_t)r * HIDDEN + j * 8);
                } else if (ch < 1024) {
                    int c2 = ch - 512, r = c2 >> 3, j = c2 & 7;
                    cp16(vo + SWZ((uint32_t)(r * 128 + j * 16)), vb + (size_t)r * HIDDEN + j * 8);
                } else {
                    int c2 = ch - 1024, r = c2 >> 4, j = c2 & 15;
                    cp16(bo + BSWZ((uint32_t)(r * 256 + j * 16)), bb + (size_t)r * SEQ + j * 4);
                }
            }
            cp_commit();
        }

        uint32_t kbuf = sb + AT_K + (uint32_t)(buf * 8192);
        uint32_t vbuf = sb + AT_V + (uint32_t)(buf * 8192);

        float sc[8][4];
        #pragma unroll
        for (int i = 0; i < 8; i++)
            #pragma unroll
            for (int j = 0; j < 4; j++) sc[i][j] = 0.f;

        #pragma unroll
        for (int np = 0; np < 4; np++) {
            #pragma unroll
            for (int kf = 0; kf < 4; kf++) {
                uint32_t b0, b1, b2, b3;
                int row = np * 16 + (l & 7) + ((l >> 4) << 3);
                int col = kf * 16 + ((l >> 3) & 1) * 8;
                ldm_x4(b0, b1, b2, b3, kbuf + SWZ((uint32_t)((row * 64 + col) * 2)));
                mma16816(sc[2 * np],     qa[kf], b0, b1);
                mma16816(sc[2 * np + 1], qa[kf], b2, b3);
            }
        }

        // P = exp(S + bias) without max-shift (scores bounded ~|10|)
        {
            const char* bsm = asm_ + AT_B + buf * 16384;
            int rb0 = w * 16 + (l >> 2);
            #pragma unroll
            for (int j = 0; j < 8; j++) {
                uint32_t o0 = (uint32_t)(rb0 * 256 + (j * 8 + 2 * (l & 3)) * 4);
                uint32_t o1 = o0 + 8 * 256;
                float2 v0 = *(const float2*)(bsm + BSWZ(o0));
                float2 v1 = *(const float2*)(bsm + BSWZ(o1));
                sc[j][0] = ex2f((sc[j][0] + v0.x) * LOG2E);
                sc[j][1] = ex2f((sc[j][1] + v0.y) * LOG2E);
                sc[j][2] = ex2f((sc[j][2] + v1.x) * LOG2E);
                sc[j][3] = ex2f((sc[j][3] + v1.y) * LOG2E);
                lrow0 += sc[j][0] + sc[j][1];
                lrow1 += sc[j][2] + sc[j][3];
            }
        }

        uint32_t pa[4][4];
        #pragma unroll
        for (int kf = 0; kf < 4; kf++) {
            pa[kf][0] = h2u(sc[2 * kf][0],     sc[2 * kf][1]);
            pa[kf][1] = h2u(sc[2 * kf][2],     sc[2 * kf][3]);
            pa[kf][2] = h2u(sc[2 * kf + 1][0], sc[2 * kf + 1][1]);
            pa[kf][3] = h2u(sc[2 * kf + 1][2], sc[2 * kf + 1][3]);
        }

        #pragma unroll
        for (int np = 0; np < 4; np++) {
            #pragma unroll
            for (int kf = 0; kf < 4; kf++) {
                uint32_t b0, b1, b2, b3;
                int row = kf * 16 + (l & 7) + (((l >> 3) & 1) << 3);
                int col = np * 16 + ((l >> 4) << 3);
                ldm_x4_t(b0, b1, b2, b3, vbuf + SWZ((uint32_t)((row * 64 + col) * 2)));
                mma16816(o[2 * np],     pa[kf], b0, b1);
                mma16816(o[2 * np + 1], pa[kf], b2, b3);
            }
        }
    }

    lrow0 += __shfl_xor_sync(0xffffffffu, lrow0, 1);
    lrow0 += __shfl_xor_sync(0xffffffffu, lrow0, 2);
    lrow1 += __shfl_xor_sync(0xffffffffu, lrow1, 1);
    lrow1 += __shfl_xor_sync(0xffffffffu, lrow1, 2);

    float inv0 = 1.f / lrow0, inv1 = 1.f / lrow1;
    float* ob = out + ((size_t)(b * SEQ + q0 + w * 16 + (l >> 2))) * HIDDEN + h * DH + 2 * (l & 3);
    #pragma unroll
    for (int dt = 0; dt < 8; dt++) {
        float2 r0 = make_float2(o[dt][0] * inv0, o[dt][1] * inv0);
        float2 r1 = make_float2(o[dt][2] * inv1, o[dt][3] * inv1);
        *(float2*)(ob + dt * 8)                      = r0;
        *(float2*)(ob + 8 * (size_t)HIDDEN + dt * 8) = r1;
    }
}

// ---------------- launch: prep forked, proj+attn serialized ----------------
extern "C" void kernel_launch(void* const* d_in, const int* in_sizes, int n_in,
                              void* d_out, int out_size) {
    (void)in_sizes; (void)n_in; (void)out_size;
    const float* q  = (const float*)d_in[0];
    const float* k  = (const float*)d_in[1];
    const float* v  = (const float*)d_in[2];
    const float* ab = (const float*)d_in[3];
    const float* Wq = (const float*)d_in[4];
    const float* bq = (const float*)d_in[5];
    const float* Aq = (const float*)d_in[6];
    const float* Bq = (const float*)d_in[7];
    const float* Wk = (const float*)d_in[8];
    const float* bk = (const float*)d_in[9];
    const float* Ak = (const float*)d_in[10];
    const float* Bk = (const float*)d_in[11];
    const float* Wv = (const float*)d_in[12];
    const float* bv = (const float*)d_in[13];
    const float* Av = (const float*)d_in[14];
    const float* Bv = (const float*)d_in[15];
    float* out = (float*)d_out;

    static cudaStream_t s1 = nullptr;
    static cudaEvent_t ev_fork, ev_w;
    static bool init_done = false;
    if (!init_done) {
        cudaStreamCreateWithFlags(&s1, cudaStreamNonBlocking);
        cudaEventCreateWithFlags(&ev_fork, cudaEventDisableTiming);
        cudaEventCreateWithFlags(&ev_w,    cudaEventDisableTiming);
        cudaFuncSetAttribute(proj_kernel, cudaFuncAttributeMaxDynamicSharedMemorySize, 2 * PJ_STAGE);
        cudaFuncSetAttribute(attn_kernel, cudaFuncAttributeMaxDynamicSharedMemorySize, AT_SMEM);
        init_done = true;
    }

    // fork: aug_w on s1, lora_augx on default; join before proj
    cudaEventRecord(ev_fork, 0);
    cudaStreamWaitEvent(s1, ev_fork, 0);
    aug_w_kernel<<<dim3(HIDDEN, 3), 256, 0, s1>>>(Wq, Bq, bq, Wk, Bk, bk, Wv, Bv, bv);
    cudaEventRecord(ev_w, s1);
    lora_augx_kernel<<<dim3(MROWS, 3), 256>>>(q, k, v, Aq, Ak, Av);
    cudaStreamWaitEvent(0, ev_w, 0);

    proj_kernel<<<dim3(3 * HIDDEN / 128, MROWS / 128), 256, 2 * PJ_STAGE>>>();

    attn_kernel<<<dim3(SEQ / 64, HEADS, BT), 128, AT_SMEM>>>(ab, out);
}